// round 2
// baseline (speedup 1.0000x reference)
#include <cuda_runtime.h>
#include <math.h>

// ---------------- Scratch (no runtime allocation allowed) ----------------
#define T_LEN 2048
#define D_COLS 2700
__device__ __align__(16) float g_tm[T_LEN * D_COLS]; // sigmoid(emb[doc] @ diags^T + bias), [T][D]
__device__ float g_scores[300];                      // per-pattern scores

__device__ __forceinline__ float sigmoidf(float x) {
    return 1.0f / (1.0f + expf(-x));
}

// ---------------- Kernel 1: gathered GEMM + bias + sigmoid ----------------
// C[m][n] = sigmoid( sum_k emb[doc[m]][k] * diags[n][k] + bias[n] )
// M=2048, N=2700, K=300. Block tile 128x128, K-tile 32, 256 threads, 8x8 per thread.
#define BM 128
#define BN 128
#define BK 32

__global__ __launch_bounds__(256) void gemm_sig_kernel(
    const int* __restrict__ doc,
    const float* __restrict__ emb,
    const float* __restrict__ diags,
    const float* __restrict__ bias)
{
    __shared__ float As[BK][BM + 4];   // transposed: [k][m]
    __shared__ float Bs[BK][BN + 4];   // transposed: [k][n]
    __shared__ int docS[BM];

    const int tid = threadIdx.x;
    const int n0 = blockIdx.x * BN;
    const int m0 = blockIdx.y * BM;

    if (tid < BM) docS[tid] = doc[m0 + tid];
    __syncthreads();

    const int tx = tid & 15;          // 0..15 -> N direction
    const int ty = tid >> 4;          // 0..15 -> M direction

    float acc[8][8];
#pragma unroll
    for (int i = 0; i < 8; i++)
#pragma unroll
        for (int j = 0; j < 8; j++) acc[i][j] = 0.0f;

    for (int k0 = 0; k0 < 300; k0 += BK) {
        // ---- load A tile (gather via doc) ----
#pragma unroll
        for (int i = 0; i < 4; i++) {
            int slot = tid + i * 256;          // 0..1023 float4 slots
            int m = slot >> 3;
            int k4 = (slot & 7) * 4;
            float4 v = make_float4(0.f, 0.f, 0.f, 0.f);
            if (k0 + k4 < 300)
                v = *(const float4*)(emb + (size_t)docS[m] * 300 + k0 + k4);
            As[k4 + 0][m] = v.x;
            As[k4 + 1][m] = v.y;
            As[k4 + 2][m] = v.z;
            As[k4 + 3][m] = v.w;
        }
        // ---- load B tile ----
#pragma unroll
        for (int i = 0; i < 4; i++) {
            int slot = tid + i * 256;
            int n = slot >> 3;
            int k4 = (slot & 7) * 4;
            int gn = n0 + n;
            float4 v = make_float4(0.f, 0.f, 0.f, 0.f);
            if (gn < D_COLS && k0 + k4 < 300)
                v = *(const float4*)(diags + (size_t)gn * 300 + k0 + k4);
            Bs[k4 + 0][n] = v.x;
            Bs[k4 + 1][n] = v.y;
            Bs[k4 + 2][n] = v.z;
            Bs[k4 + 3][n] = v.w;
        }
        __syncthreads();

#pragma unroll
        for (int kk = 0; kk < BK; kk++) {
            float4 a0 = *(const float4*)&As[kk][ty * 8];
            float4 a1 = *(const float4*)&As[kk][ty * 8 + 4];
            float4 b0 = *(const float4*)&Bs[kk][tx * 8];
            float4 b1 = *(const float4*)&Bs[kk][tx * 8 + 4];
            float a[8] = {a0.x, a0.y, a0.z, a0.w, a1.x, a1.y, a1.z, a1.w};
            float b[8] = {b0.x, b0.y, b0.z, b0.w, b1.x, b1.y, b1.z, b1.w};
#pragma unroll
            for (int i = 0; i < 8; i++)
#pragma unroll
                for (int j = 0; j < 8; j++)
                    acc[i][j] = fmaf(a[i], b[j], acc[i][j]);
        }
        __syncthreads();
    }

    // ---- epilogue: bias + sigmoid + store ----
#pragma unroll
    for (int i = 0; i < 8; i++) {
        int m = m0 + ty * 8 + i;
#pragma unroll
        for (int j = 0; j < 8; j++) {
            int n = n0 + tx * 8 + j;
            if (n < D_COLS) {
                float x = acc[i][j] + bias[n];
                g_tm[(size_t)m * D_COLS + n] = sigmoidf(x);
            }
        }
    }
}

// ---------------- Kernel 2: per-pattern sequential scan ----------------
// One thread per pattern; DEPTH-deep register ring of prefetched tm rows.
// Row layout per pattern at time t: v[0..P-1] = self row (tm_t[0,:]),
//                                   v[P..2P-1] = main row (tm_t[1,:]).
template <int P>
__device__ __forceinline__ void scan_impl(
    const float* __restrict__ eps_raw,   // [50][P-1]
    float eps_sc, float sls,
    int groupStart, int scoreOff)
{
    const int n = threadIdx.x;
    if (n >= 50) return;

    float eps[P - 1];
#pragma unroll
    for (int j = 0; j < P - 1; j++)
        eps[j] = eps_sc * sigmoidf(eps_raw[n * (P - 1) + j]);

    // Column base for this pattern: [self(P), main(P)] contiguous.
    const float* base = g_tm + groupStart + n * 2 * P;

    constexpr int DEPTH = 8;
    float2 buf[DEPTH][P];   // 2P floats per row as P float2 (8-byte aligned)

#pragma unroll
    for (int d = 0; d < DEPTH; d++) {
        const float2* rp = (const float2*)(base + (size_t)d * D_COLS);
#pragma unroll
        for (int j = 0; j < P; j++) buf[d][j] = rp[j];
    }

    float h[P];
    h[0] = 1.0f;
#pragma unroll
    for (int i = 1; i < P; i++) h[i] = 0.0f;
    float sc = 0.0f;

    for (int tb = 0; tb < T_LEN; tb += DEPTH) {
#pragma unroll
        for (int d = 0; d < DEPTH; d++) {
            const int t = tb + d;
            // unpack current row
            float v[2 * P];
#pragma unroll
            for (int j = 0; j < P; j++) {
                v[2 * j]     = buf[d][j].x;
                v[2 * j + 1] = buf[d][j].y;
            }
            // prefetch row t+DEPTH into the slot we just consumed
            const int tn = t + DEPTH;
            if (tn < T_LEN) {
                const float2* rp = (const float2*)(base + (size_t)tn * D_COLS);
#pragma unroll
                for (int j = 0; j < P; j++) buf[d][j] = rp[j];
            }
            // epsilon transitions: h[i] += h[i-1]*eps[i-1], descending (uses old h)
#pragma unroll
            for (int i = P - 1; i >= 1; --i)
                h[i] = fmaf(h[i - 1], eps[i - 1], h[i]);
            // main transitions (row 1) + scaled self loops (row 0)
            float res[P];
            res[0] = fmaf(sls * h[0], v[0], 1.0f);
#pragma unroll
            for (int i = 1; i < P; i++)
                res[i] = fmaf(h[i - 1], v[P + i - 1], sls * h[i] * v[i]);
            sc += res[P - 1];
#pragma unroll
            for (int i = 0; i < P; i++) h[i] = res[i];
        }
    }
    g_scores[scoreOff + n] = sc;
}

__global__ __launch_bounds__(64, 1) void scan_all_kernel(
    const float* e2, const float* e3, const float* e4,
    const float* e5, const float* e6, const float* e7,
    const float* __restrict__ eps_scale,
    const float* __restrict__ sls_scale)
{
    const float eps_sc = sigmoidf(eps_scale[0]);
    const float sls = sigmoidf(sls_scale[0]);
    switch (blockIdx.x) {
        case 0: scan_impl<2>(e2, eps_sc, sls,    0,   0); break;
        case 1: scan_impl<3>(e3, eps_sc, sls,  200,  50); break;
        case 2: scan_impl<4>(e4, eps_sc, sls,  500, 100); break;
        case 3: scan_impl<5>(e5, eps_sc, sls,  900, 150); break;
        case 4: scan_impl<6>(e6, eps_sc, sls, 1400, 200); break;
        case 5: scan_impl<7>(e7, eps_sc, sls, 2000, 250); break;
    }
}

// ---------------- Kernel 3: tiny MLP head ----------------
__global__ __launch_bounds__(128) void mlp_kernel(
    const float* __restrict__ w1, const float* __restrict__ b1,
    const float* __restrict__ w2, const float* __restrict__ b2,
    float* __restrict__ out)
{
    __shared__ float hsh[128];
    const int k = threadIdx.x;
    float acc = 0.0f;
    if (k < 100) {
        acc = b1[k];
        for (int j = 0; j < 300; j++)
            acc = fmaf(g_scores[j], w1[j * 100 + k], acc);
        acc = fmaxf(acc, 0.0f);
    }
    hsh[k] = (k < 100) ? acc : 0.0f;
    __syncthreads();
    if (k < 2) {
        float o = b2[k];
        for (int i = 0; i < 100; i++)
            o = fmaf(hsh[i], w2[i * 2 + k], o);
        out[k] = o;
    }
}

// ---------------- Launch ----------------
extern "C" void kernel_launch(void* const* d_in, const int* in_sizes, int n_in,
                              void* d_out, int out_size)
{
    const int*   doc       = (const int*)  d_in[0];
    const float* emb       = (const float*)d_in[1];
    const float* diags     = (const float*)d_in[2];
    const float* bias      = (const float*)d_in[3];
    const float* e2        = (const float*)d_in[4];
    const float* e3        = (const float*)d_in[5];
    const float* e4        = (const float*)d_in[6];
    const float* e5        = (const float*)d_in[7];
    const float* e6        = (const float*)d_in[8];
    const float* e7        = (const float*)d_in[9];
    const float* eps_scale = (const float*)d_in[10];
    const float* sls_scale = (const float*)d_in[11];
    const float* w1        = (const float*)d_in[12];
    const float* b1        = (const float*)d_in[13];
    const float* w2        = (const float*)d_in[14];
    const float* b2        = (const float*)d_in[15];
    float* out = (float*)d_out;

    dim3 gemm_grid((D_COLS + BN - 1) / BN, T_LEN / BM);   // (22, 16)
    gemm_sig_kernel<<<gemm_grid, 256>>>(doc, emb, diags, bias);
    scan_all_kernel<<<6, 64>>>(e2, e3, e4, e5, e6, e7, eps_scale, sls_scale);
    mlp_kernel<<<1, 128>>>(w1, b1, w2, b2, out);
}

// round 3
// speedup vs baseline: 1.7837x; 1.7837x over previous
#include <cuda_runtime.h>
#include <math.h>

// ---------------- Scratch (no runtime allocation allowed) ----------------
#define T_LEN 2048
#define D_COLS 2700
#define CH 128                      // chunk length for parallel scan
#define WARM 128                    // warm-up steps (discarded)
#define NCHUNK (T_LEN / CH)         // 16
__device__ __align__(16) float g_tm[T_LEN * D_COLS]; // sigmoid(emb[doc] @ diags^T + bias), [T][D]
__device__ float g_part[300 * NCHUNK];               // per-(pattern, chunk) partial scores

__device__ __forceinline__ float sigmoidf(float x) {
    return 1.0f / (1.0f + expf(-x));
}

// ---------------- Kernel 1: gathered GEMM + bias + sigmoid ----------------
// C[m][n] = sigmoid( sum_k emb[doc[m]][k] * diags[n][k] + bias[n] )
// M=2048, N=2700, K=300. Block tile 128x128, K-tile 32, 256 threads, 8x8 per thread.
#define BM 128
#define BN 128
#define BK 32

__global__ __launch_bounds__(256) void gemm_sig_kernel(
    const int* __restrict__ doc,
    const float* __restrict__ emb,
    const float* __restrict__ diags,
    const float* __restrict__ bias)
{
    __shared__ float As[BK][BM + 4];   // transposed: [k][m]
    __shared__ float Bs[BK][BN + 4];   // transposed: [k][n]
    __shared__ int docS[BM];

    const int tid = threadIdx.x;
    const int n0 = blockIdx.x * BN;
    const int m0 = blockIdx.y * BM;

    if (tid < BM) docS[tid] = doc[m0 + tid];
    __syncthreads();

    const int tx = tid & 15;          // 0..15 -> N direction
    const int ty = tid >> 4;          // 0..15 -> M direction

    float acc[8][8];
#pragma unroll
    for (int i = 0; i < 8; i++)
#pragma unroll
        for (int j = 0; j < 8; j++) acc[i][j] = 0.0f;

    for (int k0 = 0; k0 < 300; k0 += BK) {
        // ---- load A tile (gather via doc) ----
#pragma unroll
        for (int i = 0; i < 4; i++) {
            int slot = tid + i * 256;          // 0..1023 float4 slots
            int m = slot >> 3;
            int k4 = (slot & 7) * 4;
            float4 v = make_float4(0.f, 0.f, 0.f, 0.f);
            if (k0 + k4 < 300)
                v = *(const float4*)(emb + (size_t)docS[m] * 300 + k0 + k4);
            As[k4 + 0][m] = v.x;
            As[k4 + 1][m] = v.y;
            As[k4 + 2][m] = v.z;
            As[k4 + 3][m] = v.w;
        }
        // ---- load B tile ----
#pragma unroll
        for (int i = 0; i < 4; i++) {
            int slot = tid + i * 256;
            int n = slot >> 3;
            int k4 = (slot & 7) * 4;
            int gn = n0 + n;
            float4 v = make_float4(0.f, 0.f, 0.f, 0.f);
            if (gn < D_COLS && k0 + k4 < 300)
                v = *(const float4*)(diags + (size_t)gn * 300 + k0 + k4);
            Bs[k4 + 0][n] = v.x;
            Bs[k4 + 1][n] = v.y;
            Bs[k4 + 2][n] = v.z;
            Bs[k4 + 3][n] = v.w;
        }
        __syncthreads();

#pragma unroll
        for (int kk = 0; kk < BK; kk++) {
            float4 a0 = *(const float4*)&As[kk][ty * 8];
            float4 a1 = *(const float4*)&As[kk][ty * 8 + 4];
            float4 b0 = *(const float4*)&Bs[kk][tx * 8];
            float4 b1 = *(const float4*)&Bs[kk][tx * 8 + 4];
            float a[8] = {a0.x, a0.y, a0.z, a0.w, a1.x, a1.y, a1.z, a1.w};
            float b[8] = {b0.x, b0.y, b0.z, b0.w, b1.x, b1.y, b1.z, b1.w};
#pragma unroll
            for (int i = 0; i < 8; i++)
#pragma unroll
                for (int j = 0; j < 8; j++)
                    acc[i][j] = fmaf(a[i], b[j], acc[i][j]);
        }
        __syncthreads();
    }

    // ---- epilogue: bias + sigmoid + store ----
#pragma unroll
    for (int i = 0; i < 8; i++) {
        int m = m0 + ty * 8 + i;
#pragma unroll
        for (int j = 0; j < 8; j++) {
            int n = n0 + tx * 8 + j;
            if (n < D_COLS) {
                float x = acc[i][j] + bias[n];
                g_tm[(size_t)m * D_COLS + n] = sigmoidf(x);
            }
        }
    }
}

// ---------------- Kernel 2: chunked parallel scan ----------------
// Grid: (6 groups, NCHUNK chunks). One thread per pattern within a block.
// Each chunk warms up WARM steps from the restart state (contraction makes the
// initial condition decay below 1e-10 by 128 steps), then accumulates CH steps.
// Row layout per pattern at time t: v[0..P-1] = self row, v[P..2P-1] = main row.
template <int P>
__device__ __forceinline__ void scan_impl(
    const float* __restrict__ eps_raw,   // [50][P-1]
    float eps_sc, float sls,
    int groupStart, int scoreOff, int chunk)
{
    const int n = threadIdx.x;
    if (n >= 50) return;

    float eps[P - 1];
#pragma unroll
    for (int j = 0; j < P - 1; j++)
        eps[j] = eps_sc * sigmoidf(eps_raw[n * (P - 1) + j]);

    const float* base = g_tm + groupStart + n * 2 * P;

    const int acc_start = chunk * CH;
    int t_begin = acc_start - WARM;
    if (t_begin < 0) t_begin = 0;
    const int t_end = acc_start + CH;
    const int nsteps = t_end - t_begin;   // 128 (chunk 0) or 256; divisible by DEPTH

    constexpr int DEPTH = 8;
    float2 buf[DEPTH][P];   // ring of prefetched rows (2P floats = P float2)

#pragma unroll
    for (int d = 0; d < DEPTH; d++) {
        const float2* rp = (const float2*)(base + (size_t)(t_begin + d) * D_COLS);
#pragma unroll
        for (int j = 0; j < P; j++) buf[d][j] = rp[j];
    }

    float h[P];
    h[0] = 1.0f;
#pragma unroll
    for (int i = 1; i < P; i++) h[i] = 0.0f;
    float sc = 0.0f;

    for (int sb = 0; sb < nsteps; sb += DEPTH) {
#pragma unroll
        for (int d = 0; d < DEPTH; d++) {
            const int s = sb + d;
            const int t = t_begin + s;
            // unpack current row
            float v[2 * P];
#pragma unroll
            for (int j = 0; j < P; j++) {
                v[2 * j]     = buf[d][j].x;
                v[2 * j + 1] = buf[d][j].y;
            }
            // prefetch row t+DEPTH into the slot just consumed
            const int tn = t + DEPTH;
            if (tn < t_end) {
                const float2* rp = (const float2*)(base + (size_t)tn * D_COLS);
#pragma unroll
                for (int j = 0; j < P; j++) buf[d][j] = rp[j];
            }
            // epsilon transitions (all read pre-update h, descending order)
#pragma unroll
            for (int i = P - 1; i >= 1; --i)
                h[i] = fmaf(h[i - 1], eps[i - 1], h[i]);
            // main transitions (row 1) + scaled self loops (row 0)
            float res[P];
            res[0] = fmaf(sls * h[0], v[0], 1.0f);
#pragma unroll
            for (int i = 1; i < P; i++)
                res[i] = fmaf(h[i - 1], v[P + i - 1], sls * h[i] * v[i]);
            if (t >= acc_start) sc += res[P - 1];
#pragma unroll
            for (int i = 0; i < P; i++) h[i] = res[i];
        }
    }
    g_part[(scoreOff + n) * NCHUNK + chunk] = sc;
}

__global__ __launch_bounds__(64) void scan_all_kernel(
    const float* e2, const float* e3, const float* e4,
    const float* e5, const float* e6, const float* e7,
    const float* __restrict__ eps_scale,
    const float* __restrict__ sls_scale)
{
    const float eps_sc = sigmoidf(eps_scale[0]);
    const float sls = sigmoidf(sls_scale[0]);
    const int chunk = blockIdx.y;
    switch (blockIdx.x) {
        case 0: scan_impl<2>(e2, eps_sc, sls,    0,   0, chunk); break;
        case 1: scan_impl<3>(e3, eps_sc, sls,  200,  50, chunk); break;
        case 2: scan_impl<4>(e4, eps_sc, sls,  500, 100, chunk); break;
        case 3: scan_impl<5>(e5, eps_sc, sls,  900, 150, chunk); break;
        case 4: scan_impl<6>(e6, eps_sc, sls, 1400, 200, chunk); break;
        case 5: scan_impl<7>(e7, eps_sc, sls, 2000, 250, chunk); break;
    }
}

// ---------------- Kernel 3: partial reduction + tiny MLP head ----------------
__global__ __launch_bounds__(128) void mlp_kernel(
    const float* __restrict__ w1, const float* __restrict__ b1,
    const float* __restrict__ w2, const float* __restrict__ b2,
    float* __restrict__ out)
{
    __shared__ float ssc[300];
    __shared__ float hsh[128];
    const int k = threadIdx.x;

    // reduce chunk partials -> scores
    for (int j = k; j < 300; j += 128) {
        float a = 0.0f;
#pragma unroll
        for (int c = 0; c < NCHUNK; c++) a += g_part[j * NCHUNK + c];
        ssc[j] = a;
    }
    __syncthreads();

    float acc = 0.0f;
    if (k < 100) {
        acc = b1[k];
        for (int j = 0; j < 300; j++)
            acc = fmaf(ssc[j], w1[j * 100 + k], acc);
        acc = fmaxf(acc, 0.0f);
    }
    hsh[k] = (k < 100) ? acc : 0.0f;
    __syncthreads();
    if (k < 2) {
        float o = b2[k];
        for (int i = 0; i < 100; i++)
            o = fmaf(hsh[i], w2[i * 2 + k], o);
        out[k] = o;
    }
}

// ---------------- Launch ----------------
extern "C" void kernel_launch(void* const* d_in, const int* in_sizes, int n_in,
                              void* d_out, int out_size)
{
    const int*   doc       = (const int*)  d_in[0];
    const float* emb       = (const float*)d_in[1];
    const float* diags     = (const float*)d_in[2];
    const float* bias      = (const float*)d_in[3];
    const float* e2        = (const float*)d_in[4];
    const float* e3        = (const float*)d_in[5];
    const float* e4        = (const float*)d_in[6];
    const float* e5        = (const float*)d_in[7];
    const float* e6        = (const float*)d_in[8];
    const float* e7        = (const float*)d_in[9];
    const float* eps_scale = (const float*)d_in[10];
    const float* sls_scale = (const float*)d_in[11];
    const float* w1        = (const float*)d_in[12];
    const float* b1        = (const float*)d_in[13];
    const float* w2        = (const float*)d_in[14];
    const float* b2        = (const float*)d_in[15];
    float* out = (float*)d_out;

    dim3 gemm_grid((D_COLS + BN - 1) / BN, T_LEN / BM);   // (22, 16)
    gemm_sig_kernel<<<gemm_grid, 256>>>(doc, emb, diags, bias);
    scan_all_kernel<<<dim3(6, NCHUNK), 64>>>(e2, e3, e4, e5, e6, e7, eps_scale, sls_scale);
    mlp_kernel<<<1, 128>>>(w1, b1, w2, b2, out);
}

// round 5
// speedup vs baseline: 2.3623x; 1.3244x over previous
#include <cuda_runtime.h>
#include <math.h>

// ---------------- Scratch (no runtime allocation allowed) ----------------
#define T_LEN 2048
#define D_COLS 2700
#define CH 128
#define WARM 128
#define NCHUNK (T_LEN / CH)         // 16
__device__ __align__(16) float g_tm[T_LEN * D_COLS];
__device__ float g_part[300 * NCHUNK];

__device__ __forceinline__ float sigmoidf(float x) {
    return 1.0f / (1.0f + expf(-x));
}

// =======================================================================
// Kernel 1: gathered GEMM via mma.sync 3xTF32 + bias + sigmoid
//   C[m][n] = sigmoid( sum_k emb[doc[m]][k] * diags[n][k] + bias[n] )
//   M=2048, N=2700, K=300 (padded to 304). CTA tile 128x128, BK=16.
//   8 warps (2m x 4n), warp tile 64x32 = 4x4 m16n8k8 fragments.
// =======================================================================
#define AST 20                      // smem row stride in floats (conflict-free)
#define NKS 19                      // ceil(304/16)

__device__ __forceinline__ unsigned cvt_tf32(float x) {
    unsigned b; asm("cvt.rna.tf32.f32 %0, %1;" : "=r"(b) : "f"(x));
    return b;
}
__device__ __forceinline__ void mma_tf32(float* c, const unsigned* a, const unsigned* b) {
    asm volatile("mma.sync.aligned.m16n8k8.row.col.f32.tf32.tf32.f32 "
        "{%0,%1,%2,%3}, {%4,%5,%6,%7}, {%8,%9}, {%0,%1,%2,%3};"
        : "+f"(c[0]), "+f"(c[1]), "+f"(c[2]), "+f"(c[3])
        : "r"(a[0]), "r"(a[1]), "r"(a[2]), "r"(a[3]), "r"(b[0]), "r"(b[1]));
}

__global__ __launch_bounds__(256) void gemm_mma_kernel(
    const int* __restrict__ doc,
    const float* __restrict__ emb,
    const float* __restrict__ diags,
    const float* __restrict__ bias)
{
    extern __shared__ float sm[];
    // 4 tile buffers: As0, Bs0, As1, Bs1 (each 128*AST floats); epilogue reuses sm.
    float* Abuf[2] = { sm,            sm + 5120 };
    float* Bbuf[2] = { sm + 2560,     sm + 7680 };
    __shared__ int docS[128];

    const int tid = threadIdx.x;
    const int wid = tid >> 5;
    const int lane = tid & 31;
    const int wm = wid >> 2;          // 0..1 : m half
    const int wn = wid & 3;           // 0..3 : n quarter
    const int grp = lane >> 2;        // 0..7
    const int tig = lane & 3;         // 0..3
    const int n0 = blockIdx.x * 128;
    const int m0 = blockIdx.y * 128;

    if (tid < 128) docS[tid] = doc[m0 + tid];
    __syncthreads();

    float acc[4][4][4];
#pragma unroll
    for (int i = 0; i < 4; i++)
#pragma unroll
        for (int j = 0; j < 4; j++)
#pragma unroll
            for (int r = 0; r < 4; r++) acc[i][j][r] = 0.0f;

    const float4 fz = make_float4(0.f, 0.f, 0.f, 0.f);
    float4 ra[2], rb[2];

    // ---- prologue: stage 0 ----
#pragma unroll
    for (int i = 0; i < 2; i++) {
        int slot = tid + i * 256;          // 512 float4 slots
        int m = slot >> 2;
        int k4 = (slot & 3) * 4;
        bool kok = k4 < 300;               // k0 = 0
        ra[i] = kok ? *(const float4*)(emb + (size_t)docS[m] * 300 + k4) : fz;
        int gn = n0 + m;
        rb[i] = (kok && gn < D_COLS) ? *(const float4*)(diags + (size_t)gn * 300 + k4) : fz;
    }
#pragma unroll
    for (int i = 0; i < 2; i++) {
        int slot = tid + i * 256;
        int m = slot >> 2;
        int k4 = (slot & 3) * 4;
        *(float4*)(Abuf[0] + m * AST + k4) = ra[i];
        *(float4*)(Bbuf[0] + m * AST + k4) = rb[i];
    }
    __syncthreads();

    for (int c = 0; c < NKS; c++) {
        // prefetch next stage into registers
        if (c + 1 < NKS) {
            const int k0 = (c + 1) * 16;
#pragma unroll
            for (int i = 0; i < 2; i++) {
                int slot = tid + i * 256;
                int m = slot >> 2;
                int k4 = (slot & 3) * 4;
                bool kok = (k0 + k4) < 300;
                ra[i] = kok ? *(const float4*)(emb + (size_t)docS[m] * 300 + k0 + k4) : fz;
                int gn = n0 + m;
                rb[i] = (kok && gn < D_COLS) ? *(const float4*)(diags + (size_t)gn * 300 + k0 + k4) : fz;
            }
        }
        // compute on current buffer
        {
            const float* As = Abuf[c & 1];
            const float* Bs = Bbuf[c & 1];
#pragma unroll
            for (int s = 0; s < 2; s++) {
                const int kb = s * 8;
                unsigned bh[4][2], bl[4][2];
#pragma unroll
                for (int nt = 0; nt < 4; nt++) {
                    const int br = (wn * 32 + nt * 8 + grp) * AST + kb + tig;
#pragma unroll
                    for (int j = 0; j < 2; j++) {
                        float v = Bs[br + j * 4];
                        unsigned h = cvt_tf32(v);
                        bh[nt][j] = h;
                        bl[nt][j] = cvt_tf32(v - __uint_as_float(h));
                    }
                }
#pragma unroll
                for (int mt = 0; mt < 4; mt++) {
                    const int ar = (wm * 64 + mt * 16 + grp) * AST + kb + tig;
                    float av[4];
                    av[0] = As[ar];
                    av[1] = As[ar + 8 * AST];
                    av[2] = As[ar + 4];
                    av[3] = As[ar + 8 * AST + 4];
                    unsigned ah[4], al[4];
#pragma unroll
                    for (int j = 0; j < 4; j++) {
                        ah[j] = cvt_tf32(av[j]);
                        al[j] = cvt_tf32(av[j] - __uint_as_float(ah[j]));
                    }
#pragma unroll
                    for (int nt = 0; nt < 4; nt++) {
                        mma_tf32(acc[mt][nt], ah, bh[nt]);
                        mma_tf32(acc[mt][nt], al, bh[nt]);
                        mma_tf32(acc[mt][nt], ah, bl[nt]);
                    }
                }
            }
        }
        // store prefetched stage
        if (c + 1 < NKS) {
#pragma unroll
            for (int i = 0; i < 2; i++) {
                int slot = tid + i * 256;
                int m = slot >> 2;
                int k4 = (slot & 3) * 4;
                *(float4*)(Abuf[(c + 1) & 1] + m * AST + k4) = ra[i];
                *(float4*)(Bbuf[(c + 1) & 1] + m * AST + k4) = rb[i];
            }
        }
        __syncthreads();
    }

    // ---- epilogue: two 64-row halves via smem, coalesced stores ----
    float* smep = sm;   // 64 x 132 floats = 33792 B (buffers dead now)
    for (int p = 0; p < 2; p++) {
        if (wm == p) {
#pragma unroll
            for (int mt = 0; mt < 4; mt++) {
                const int r0 = mt * 16 + grp;
#pragma unroll
                for (int nt = 0; nt < 4; nt++) {
                    const int cb = wn * 32 + nt * 8 + 2 * tig;
                    smep[r0 * 132 + cb]           = acc[mt][nt][0];
                    smep[r0 * 132 + cb + 1]       = acc[mt][nt][1];
                    smep[(r0 + 8) * 132 + cb]     = acc[mt][nt][2];
                    smep[(r0 + 8) * 132 + cb + 1] = acc[mt][nt][3];
                }
            }
        }
        __syncthreads();
#pragma unroll
        for (int i = 0; i < 8; i++) {
            int slot = tid + i * 256;         // 2048 float4 slots
            int r = slot >> 5;
            int c4 = (slot & 31) * 4;
            int gn = n0 + c4;
            if (gn < D_COLS) {                // 2700 % 4 == 0 -> whole-float4 validity
                float4 bv = *(const float4*)(bias + gn);
                float4 o;
                o.x = 1.0f / (1.0f + __expf(-(smep[r * 132 + c4]     + bv.x)));
                o.y = 1.0f / (1.0f + __expf(-(smep[r * 132 + c4 + 1] + bv.y)));
                o.z = 1.0f / (1.0f + __expf(-(smep[r * 132 + c4 + 2] + bv.z)));
                o.w = 1.0f / (1.0f + __expf(-(smep[r * 132 + c4 + 3] + bv.w)));
                *(float4*)(g_tm + (size_t)(m0 + p * 64 + r) * D_COLS + gn) = o;
            }
        }
        __syncthreads();
    }
}

// =======================================================================
// Kernel 2: chunked parallel scan (unchanged)
// =======================================================================
template <int P>
__device__ __forceinline__ void scan_impl(
    const float* __restrict__ eps_raw,
    float eps_sc, float sls,
    int groupStart, int scoreOff, int chunk)
{
    const int n = threadIdx.x;
    if (n >= 50) return;

    float eps[P - 1];
#pragma unroll
    for (int j = 0; j < P - 1; j++)
        eps[j] = eps_sc * sigmoidf(eps_raw[n * (P - 1) + j]);

    const float* base = g_tm + groupStart + n * 2 * P;

    const int acc_start = chunk * CH;
    int t_begin = acc_start - WARM;
    if (t_begin < 0) t_begin = 0;
    const int t_end = acc_start + CH;
    const int nsteps = t_end - t_begin;

    constexpr int DEPTH = 8;
    float2 buf[DEPTH][P];

#pragma unroll
    for (int d = 0; d < DEPTH; d++) {
        const float2* rp = (const float2*)(base + (size_t)(t_begin + d) * D_COLS);
#pragma unroll
        for (int j = 0; j < P; j++) buf[d][j] = rp[j];
    }

    float h[P];
    h[0] = 1.0f;
#pragma unroll
    for (int i = 1; i < P; i++) h[i] = 0.0f;
    float sc = 0.0f;

    for (int sb2 = 0; sb2 < nsteps; sb2 += DEPTH) {
#pragma unroll
        for (int d = 0; d < DEPTH; d++) {
            const int t = t_begin + sb2 + d;
            float v[2 * P];
#pragma unroll
            for (int j = 0; j < P; j++) {
                v[2 * j]     = buf[d][j].x;
                v[2 * j + 1] = buf[d][j].y;
            }
            const int tn = t + DEPTH;
            if (tn < t_end) {
                const float2* rp = (const float2*)(base + (size_t)tn * D_COLS);
#pragma unroll
                for (int j = 0; j < P; j++) buf[d][j] = rp[j];
            }
#pragma unroll
            for (int i = P - 1; i >= 1; --i)
                h[i] = fmaf(h[i - 1], eps[i - 1], h[i]);
            float res[P];
            res[0] = fmaf(sls * h[0], v[0], 1.0f);
#pragma unroll
            for (int i = 1; i < P; i++)
                res[i] = fmaf(h[i - 1], v[P + i - 1], sls * h[i] * v[i]);
            if (t >= acc_start) sc += res[P - 1];
#pragma unroll
            for (int i = 0; i < P; i++) h[i] = res[i];
        }
    }
    g_part[(scoreOff + n) * NCHUNK + chunk] = sc;
}

__global__ __launch_bounds__(64) void scan_all_kernel(
    const float* e2, const float* e3, const float* e4,
    const float* e5, const float* e6, const float* e7,
    const float* __restrict__ eps_scale,
    const float* __restrict__ sls_scale)
{
    const float eps_sc = sigmoidf(eps_scale[0]);
    const float sls = sigmoidf(sls_scale[0]);
    const int chunk = blockIdx.y;
    switch (blockIdx.x) {
        case 0: scan_impl<2>(e2, eps_sc, sls,    0,   0, chunk); break;
        case 1: scan_impl<3>(e3, eps_sc, sls,  200,  50, chunk); break;
        case 2: scan_impl<4>(e4, eps_sc, sls,  500, 100, chunk); break;
        case 3: scan_impl<5>(e5, eps_sc, sls,  900, 150, chunk); break;
        case 4: scan_impl<6>(e6, eps_sc, sls, 1400, 200, chunk); break;
        case 5: scan_impl<7>(e7, eps_sc, sls, 2000, 250, chunk); break;
    }
}

// ---------------- Kernel 3: partial reduction + tiny MLP head ----------------
__global__ __launch_bounds__(128) void mlp_kernel(
    const float* __restrict__ w1, const float* __restrict__ b1,
    const float* __restrict__ w2, const float* __restrict__ b2,
    float* __restrict__ out)
{
    __shared__ float ssc[300];
    __shared__ float hsh[128];
    const int k = threadIdx.x;

    for (int j = k; j < 300; j += 128) {
        float a = 0.0f;
#pragma unroll
        for (int c = 0; c < NCHUNK; c++) a += g_part[j * NCHUNK + c];
        ssc[j] = a;
    }
    __syncthreads();

    float acc = 0.0f;
    if (k < 100) {
        acc = b1[k];
        for (int j = 0; j < 300; j++)
            acc = fmaf(ssc[j], w1[j * 100 + k], acc);
        acc = fmaxf(acc, 0.0f);
    }
    hsh[k] = (k < 100) ? acc : 0.0f;
    __syncthreads();
    if (k < 2) {
        float o = b2[k];
        for (int i = 0; i < 100; i++)
            o = fmaf(hsh[i], w2[i * 2 + k], o);
        out[k] = o;
    }
}

// ---------------- Launch ----------------
extern "C" void kernel_launch(void* const* d_in, const int* in_sizes, int n_in,
                              void* d_out, int out_size)
{
    const int*   doc       = (const int*)  d_in[0];
    const float* emb       = (const float*)d_in[1];
    const float* diags     = (const float*)d_in[2];
    const float* bias      = (const float*)d_in[3];
    const float* e2        = (const float*)d_in[4];
    const float* e3        = (const float*)d_in[5];
    const float* e4        = (const float*)d_in[6];
    const float* e5        = (const float*)d_in[7];
    const float* e6        = (const float*)d_in[8];
    const float* e7        = (const float*)d_in[9];
    const float* eps_scale = (const float*)d_in[10];
    const float* sls_scale = (const float*)d_in[11];
    const float* w1        = (const float*)d_in[12];
    const float* b1        = (const float*)d_in[13];
    const float* w2        = (const float*)d_in[14];
    const float* b2        = (const float*)d_in[15];
    float* out = (float*)d_out;

    const int smem_bytes = 4 * 128 * AST * sizeof(float);   // 40960
    gemm_mma_kernel<<<dim3(22, 16), 256, smem_bytes>>>(doc, emb, diags, bias);
    scan_all_kernel<<<dim3(6, NCHUNK), 64>>>(e2, e3, e4, e5, e6, e7, eps_scale, sls_scale);
    mlp_kernel<<<1, 128>>>(w1, b1, w2, b2, out);
}

// round 8
// speedup vs baseline: 3.3961x; 1.4376x over previous
#include <cuda_runtime.h>
#include <math.h>

// ---------------- Scratch (no runtime allocation allowed) ----------------
#define T_LEN 2048
#define D_COLS 2700
#define CH 128
#define WARM 128
#define NCHUNK (T_LEN / CH)         // 16
__device__ __align__(16) float g_tm[T_LEN * D_COLS];
__device__ float g_part[300 * NCHUNK];

__device__ __forceinline__ float sigmoidf(float x) {
    return 1.0f / (1.0f + expf(-x));
}

// =======================================================================
// Kernel 1: gathered GEMM via mma.sync bf16 3-term split + bias + sigmoid
//   C[m][n] = sigmoid( sum_k emb[doc[m]][k] * diags[n][k] + bias[n] )
//   M=2048, N=2700, K=300 (pad 304). CTA 128x128, BK=16, 19 stages.
//   8 warps (2m x 4n), warp tile 64x32 = 4x4 m16n8k16 fragments.
//   Producer splits f32 -> (bf16 hi, bf16 mid) ONCE into smem; consumer is
//   pure LDS.64 + HMMA. Terms: ah*bh + am*bh + ah*bm.
// =======================================================================
#define NKS 19
#define RSTRIDE 24                  // smem row stride in u32 (96B): LDS.64 conflict-free
#define BUFU32 (128 * RSTRIDE)      // 3072 u32 = 12288 B per operand buffer
#define SMEM_BYTES (4 * BUFU32 * 4) // 49152 (Ah0,Bh0,Ah1,Bh1) -- needs opt-in

// split x,y (k-even, k-odd) into packed bf16 hi-pair and mid-pair
__device__ __forceinline__ void bsplit2(float x, float y, unsigned& hp, unsigned& mp) {
    asm("cvt.rn.bf16x2.f32 %0, %1, %2;" : "=r"(hp) : "f"(y), "f"(x));
    float hx = __uint_as_float(hp << 16);
    float hy = __uint_as_float(hp & 0xFFFF0000u);
    asm("cvt.rn.bf16x2.f32 %0, %1, %2;" : "=r"(mp) : "f"(y - hy), "f"(x - hx));
}

__device__ __forceinline__ void mma_bf16(float* c, const unsigned* a, const unsigned* b) {
    asm volatile("mma.sync.aligned.m16n8k16.row.col.f32.bf16.bf16.f32 "
        "{%0,%1,%2,%3}, {%4,%5,%6,%7}, {%8,%9}, {%0,%1,%2,%3};"
        : "+f"(c[0]), "+f"(c[1]), "+f"(c[2]), "+f"(c[3])
        : "r"(a[0]), "r"(a[1]), "r"(a[2]), "r"(a[3]), "r"(b[0]), "r"(b[1]));
}

__global__ __launch_bounds__(256, 2) void gemm_mma_kernel(
    const int* __restrict__ doc,
    const float* __restrict__ emb,
    const float* __restrict__ diags,
    const float* __restrict__ bias)
{
    extern __shared__ unsigned sm[];
    unsigned* Abuf[2] = { sm,              sm + 2 * BUFU32 };
    unsigned* Bbuf[2] = { sm + BUFU32,     sm + 3 * BUFU32 };
    __shared__ int docS[128];

    const int tid = threadIdx.x;
    const int wid = tid >> 5;
    const int lane = tid & 31;
    const int wm = wid >> 2;          // 0..1 : m half
    const int wn = wid & 3;           // 0..3 : n quarter
    const int grp = lane >> 2;        // 0..7
    const int tig = lane & 3;         // 0..3
    const int n0 = blockIdx.x * 128;
    const int m0 = blockIdx.y * 128;

    if (tid < 128) docS[tid] = doc[m0 + tid];
    __syncthreads();

    float acc[4][4][4];
#pragma unroll
    for (int i = 0; i < 4; i++)
#pragma unroll
        for (int j = 0; j < 4; j++)
#pragma unroll
            for (int r = 0; r < 4; r++) acc[i][j][r] = 0.0f;

    const float4 fz = make_float4(0.f, 0.f, 0.f, 0.f);
    float4 ra[2], rb[2];

    // ---- prologue: stage 0 load ----
#pragma unroll
    for (int i = 0; i < 2; i++) {
        int slot = tid + i * 256;
        int row = slot >> 2;
        int k4 = (slot & 3) * 4;
        bool kok = k4 < 300;
        ra[i] = kok ? *(const float4*)(emb + (size_t)docS[row] * 300 + k4) : fz;
        int gn = n0 + row;
        rb[i] = (kok && gn < D_COLS) ? *(const float4*)(diags + (size_t)gn * 300 + k4) : fz;
    }
    // convert + store stage 0
#pragma unroll
    for (int i = 0; i < 2; i++) {
        int slot = tid + i * 256;
        int row = slot >> 2;
        int k4 = (slot & 3) * 4;
        unsigned h01, m01, h23, m23;
        bsplit2(ra[i].x, ra[i].y, h01, m01);
        bsplit2(ra[i].z, ra[i].w, h23, m23);
        *(uint4*)(Abuf[0] + row * RSTRIDE + k4) = make_uint4(h01, m01, h23, m23);
        bsplit2(rb[i].x, rb[i].y, h01, m01);
        bsplit2(rb[i].z, rb[i].w, h23, m23);
        *(uint4*)(Bbuf[0] + row * RSTRIDE + k4) = make_uint4(h01, m01, h23, m23);
    }
    __syncthreads();

    for (int c = 0; c < NKS; c++) {
        // prefetch next stage into registers
        if (c + 1 < NKS) {
            const int k0 = (c + 1) * 16;
#pragma unroll
            for (int i = 0; i < 2; i++) {
                int slot = tid + i * 256;
                int row = slot >> 2;
                int k4 = (slot & 3) * 4;
                bool kok = (k0 + k4) < 300;
                ra[i] = kok ? *(const float4*)(emb + (size_t)docS[row] * 300 + k0 + k4) : fz;
                int gn = n0 + row;
                rb[i] = (kok && gn < D_COLS) ? *(const float4*)(diags + (size_t)gn * 300 + k0 + k4) : fz;
            }
        }
        // ---- compute on current buffers: pure LDS.64 + HMMA ----
        {
            const unsigned* As = Abuf[c & 1];
            const unsigned* Bs = Bbuf[c & 1];
            unsigned bh[4][2], bm[4][2];
#pragma unroll
            for (int nt = 0; nt < 4; nt++) {
                const unsigned* p = Bs + (wn * 32 + nt * 8 + grp) * RSTRIDE + tig * 2;
                uint2 v0 = *(const uint2*)p;         // k-pair tig
                uint2 v1 = *(const uint2*)(p + 8);   // k-pair tig+4
                bh[nt][0] = v0.x; bm[nt][0] = v0.y;
                bh[nt][1] = v1.x; bm[nt][1] = v1.y;
            }
#pragma unroll
            for (int mt = 0; mt < 4; mt++) {
                const unsigned* p = As + (wm * 64 + mt * 16 + grp) * RSTRIDE + tig * 2;
                uint2 a0 = *(const uint2*)p;
                uint2 a1 = *(const uint2*)(p + 8 * RSTRIDE);
                uint2 a2 = *(const uint2*)(p + 8);
                uint2 a3 = *(const uint2*)(p + 8 * RSTRIDE + 8);
                unsigned ah[4] = { a0.x, a1.x, a2.x, a3.x };
                unsigned am[4] = { a0.y, a1.y, a2.y, a3.y };
#pragma unroll
                for (int nt = 0; nt < 4; nt++) {
                    mma_bf16(acc[mt][nt], ah, bh[nt]);
                    mma_bf16(acc[mt][nt], am, bh[nt]);
                    mma_bf16(acc[mt][nt], ah, bm[nt]);
                }
            }
        }
        // ---- convert + store prefetched stage ----
        if (c + 1 < NKS) {
#pragma unroll
            for (int i = 0; i < 2; i++) {
                int slot = tid + i * 256;
                int row = slot >> 2;
                int k4 = (slot & 3) * 4;
                unsigned h01, m01, h23, m23;
                bsplit2(ra[i].x, ra[i].y, h01, m01);
                bsplit2(ra[i].z, ra[i].w, h23, m23);
                *(uint4*)(Abuf[(c + 1) & 1] + row * RSTRIDE + k4) = make_uint4(h01, m01, h23, m23);
                bsplit2(rb[i].x, rb[i].y, h01, m01);
                bsplit2(rb[i].z, rb[i].w, h23, m23);
                *(uint4*)(Bbuf[(c + 1) & 1] + row * RSTRIDE + k4) = make_uint4(h01, m01, h23, m23);
            }
        }
        __syncthreads();
    }

    // ---- epilogue: two 64-row halves via smem, coalesced stores ----
    float* smep = (float*)sm;   // 64 x 132 floats = 33792 B (buffers dead)
    for (int p = 0; p < 2; p++) {
        if (wm == p) {
#pragma unroll
            for (int mt = 0; mt < 4; mt++) {
                const int r0 = mt * 16 + grp;
#pragma unroll
                for (int nt = 0; nt < 4; nt++) {
                    const int cb = wn * 32 + nt * 8 + 2 * tig;
                    smep[r0 * 132 + cb]           = acc[mt][nt][0];
                    smep[r0 * 132 + cb + 1]       = acc[mt][nt][1];
                    smep[(r0 + 8) * 132 + cb]     = acc[mt][nt][2];
                    smep[(r0 + 8) * 132 + cb + 1] = acc[mt][nt][3];
                }
            }
        }
        __syncthreads();
#pragma unroll
        for (int i = 0; i < 8; i++) {
            int slot = tid + i * 256;         // 2048 float4 slots
            int r = slot >> 5;
            int c4 = (slot & 31) * 4;
            int gn = n0 + c4;
            if (gn < D_COLS) {                // 2700 % 4 == 0 -> whole-float4 validity
                float4 bv = *(const float4*)(bias + gn);
                float4 o;
                o.x = 1.0f / (1.0f + __expf(-(smep[r * 132 + c4]     + bv.x)));
                o.y = 1.0f / (1.0f + __expf(-(smep[r * 132 + c4 + 1] + bv.y)));
                o.z = 1.0f / (1.0f + __expf(-(smep[r * 132 + c4 + 2] + bv.z)));
                o.w = 1.0f / (1.0f + __expf(-(smep[r * 132 + c4 + 3] + bv.w)));
                *(float4*)(g_tm + (size_t)(m0 + p * 64 + r) * D_COLS + gn) = o;
            }
        }
        __syncthreads();
    }
}

// =======================================================================
// Kernel 2: chunked parallel scan (unchanged)
// =======================================================================
template <int P>
__device__ __forceinline__ void scan_impl(
    const float* __restrict__ eps_raw,
    float eps_sc, float sls,
    int groupStart, int scoreOff, int chunk)
{
    const int n = threadIdx.x;
    if (n >= 50) return;

    float eps[P - 1];
#pragma unroll
    for (int j = 0; j < P - 1; j++)
        eps[j] = eps_sc * sigmoidf(eps_raw[n * (P - 1) + j]);

    const float* base = g_tm + groupStart + n * 2 * P;

    const int acc_start = chunk * CH;
    int t_begin = acc_start - WARM;
    if (t_begin < 0) t_begin = 0;
    const int t_end = acc_start + CH;
    const int nsteps = t_end - t_begin;

    constexpr int DEPTH = 8;
    float2 buf[DEPTH][P];

#pragma unroll
    for (int d = 0; d < DEPTH; d++) {
        const float2* rp = (const float2*)(base + (size_t)(t_begin + d) * D_COLS);
#pragma unroll
        for (int j = 0; j < P; j++) buf[d][j] = rp[j];
    }

    float h[P];
    h[0] = 1.0f;
#pragma unroll
    for (int i = 1; i < P; i++) h[i] = 0.0f;
    float sc = 0.0f;

    for (int sb2 = 0; sb2 < nsteps; sb2 += DEPTH) {
#pragma unroll
        for (int d = 0; d < DEPTH; d++) {
            const int t = t_begin + sb2 + d;
            float v[2 * P];
#pragma unroll
            for (int j = 0; j < P; j++) {
                v[2 * j]     = buf[d][j].x;
                v[2 * j + 1] = buf[d][j].y;
            }
            const int tn = t + DEPTH;
            if (tn < t_end) {
                const float2* rp = (const float2*)(base + (size_t)tn * D_COLS);
#pragma unroll
                for (int j = 0; j < P; j++) buf[d][j] = rp[j];
            }
#pragma unroll
            for (int i = P - 1; i >= 1; --i)
                h[i] = fmaf(h[i - 1], eps[i - 1], h[i]);
            float res[P];
            res[0] = fmaf(sls * h[0], v[0], 1.0f);
#pragma unroll
            for (int i = 1; i < P; i++)
                res[i] = fmaf(h[i - 1], v[P + i - 1], sls * h[i] * v[i]);
            if (t >= acc_start) sc += res[P - 1];
#pragma unroll
            for (int i = 0; i < P; i++) h[i] = res[i];
        }
    }
    g_part[(scoreOff + n) * NCHUNK + chunk] = sc;
}

__global__ __launch_bounds__(64) void scan_all_kernel(
    const float* e2, const float* e3, const float* e4,
    const float* e5, const float* e6, const float* e7,
    const float* __restrict__ eps_scale,
    const float* __restrict__ sls_scale)
{
    const float eps_sc = sigmoidf(eps_scale[0]);
    const float sls = sigmoidf(sls_scale[0]);
    const int chunk = blockIdx.y;
    switch (blockIdx.x) {
        case 0: scan_impl<2>(e2, eps_sc, sls,    0,   0, chunk); break;
        case 1: scan_impl<3>(e3, eps_sc, sls,  200,  50, chunk); break;
        case 2: scan_impl<4>(e4, eps_sc, sls,  500, 100, chunk); break;
        case 3: scan_impl<5>(e5, eps_sc, sls,  900, 150, chunk); break;
        case 4: scan_impl<6>(e6, eps_sc, sls, 1400, 200, chunk); break;
        case 5: scan_impl<7>(e7, eps_sc, sls, 2000, 250, chunk); break;
    }
}

// ---------------- Kernel 3: partial reduction + tiny MLP head ----------------
__global__ __launch_bounds__(128) void mlp_kernel(
    const float* __restrict__ w1, const float* __restrict__ b1,
    const float* __restrict__ w2, const float* __restrict__ b2,
    float* __restrict__ out)
{
    __shared__ float ssc[300];
    __shared__ float hsh[128];
    const int k = threadIdx.x;

    for (int j = k; j < 300; j += 128) {
        float a = 0.0f;
#pragma unroll
        for (int c = 0; c < NCHUNK; c++) a += g_part[j * NCHUNK + c];
        ssc[j] = a;
    }
    __syncthreads();

    float acc = 0.0f;
    if (k < 100) {
        acc = b1[k];
        for (int j = 0; j < 300; j++)
            acc = fmaf(ssc[j], w1[j * 100 + k], acc);
        acc = fmaxf(acc, 0.0f);
    }
    hsh[k] = (k < 100) ? acc : 0.0f;
    __syncthreads();
    if (k < 2) {
        float o = b2[k];
        for (int i = 0; i < 100; i++)
            o = fmaf(hsh[i], w2[i * 2 + k], o);
        out[k] = o;
    }
}

// ---------------- Launch ----------------
extern "C" void kernel_launch(void* const* d_in, const int* in_sizes, int n_in,
                              void* d_out, int out_size)
{
    const int*   doc       = (const int*)  d_in[0];
    const float* emb       = (const float*)d_in[1];
    const float* diags     = (const float*)d_in[2];
    const float* bias      = (const float*)d_in[3];
    const float* e2        = (const float*)d_in[4];
    const float* e3        = (const float*)d_in[5];
    const float* e4        = (const float*)d_in[6];
    const float* e5        = (const float*)d_in[7];
    const float* e6        = (const float*)d_in[8];
    const float* e7        = (const float*)d_in[9];
    const float* eps_scale = (const float*)d_in[10];
    const float* sls_scale = (const float*)d_in[11];
    const float* w1        = (const float*)d_in[12];
    const float* b1        = (const float*)d_in[13];
    const float* w2        = (const float*)d_in[14];
    const float* b2        = (const float*)d_in[15];
    float* out = (float*)d_out;

    // Opt-in for >48KB-default shared memory (host-side attribute, capture-legal).
    static int smem_set = 0;
    if (!smem_set) {
        cudaFuncSetAttribute(gemm_mma_kernel,
                             cudaFuncAttributeMaxDynamicSharedMemorySize, SMEM_BYTES);
        smem_set = 1;
    }

    gemm_mma_kernel<<<dim3(22, 16), 256, SMEM_BYTES>>>(doc, emb, diags, bias);
    scan_all_kernel<<<dim3(6, NCHUNK), 64>>>(e2, e3, e4, e5, e6, e7, eps_scale, sls_scale);
    mlp_kernel<<<1, 128>>>(w1, b1, w2, b2, out);
}